// round 2
// baseline (speedup 1.0000x reference)
#include <cuda_runtime.h>
#include <cstdint>

// Problem constants
#define CC   128
#define HH   64
#define WW   64
#define BB   8
#define EE   8
#define NG   4     // gates
#define HWPIX 4096 // 64*64
#define IMG  524288 // 128*64*64
#define YSZ  4194304 // 8*128*64*64

// device scratch (no allocs allowed)
__device__ float g_x0[BB * CC];          // batch-mean features
__device__ float g_w[NG * BB * EE];      // dense gate weights (0 => skip)

// ---------------------------------------------------------------------------
// Kernel 1: x0[b][c] = mean over H,W
// ---------------------------------------------------------------------------
__global__ void mean_kernel(const float* __restrict__ x) {
    int bc = blockIdx.x;                 // 0..1023 = b*128+c
    const float* p = x + (size_t)bc * HWPIX;
    float s = 0.f;
    for (int i = threadIdx.x; i < HWPIX; i += 256) s += p[i];
    for (int o = 16; o; o >>= 1) s += __shfl_xor_sync(0xffffffffu, s, o);
    __shared__ float sm[8];
    if ((threadIdx.x & 31) == 0) sm[threadIdx.x >> 5] = s;
    __syncthreads();
    if (threadIdx.x < 8) {
        float v = sm[threadIdx.x];
        for (int o = 4; o; o >>= 1) v += __shfl_xor_sync(0xffu, v, o);
        if (threadIdx.x == 0) g_x0[bc] = v * (1.0f / 4096.0f);
    }
}

// ---------------------------------------------------------------------------
// Kernel 2: gates. 1 block, 32 threads; lane = (g,b). Writes g_w and loss.
// ---------------------------------------------------------------------------
__global__ void gate_kernel(const float* __restrict__ g1, const float* __restrict__ g2,
                            const float* __restrict__ g3, const float* __restrict__ g4,
                            float* __restrict__ loss_out) {
    int lane = threadIdx.x;
    int g = lane >> 3, b = lane & 7;
    const float* G = (g == 0) ? g1 : (g == 1) ? g2 : (g == 2) ? g3 : g4;
    const float* x0 = &g_x0[b * CC];

    float lg[8];
#pragma unroll
    for (int e = 0; e < 8; e++) lg[e] = 0.f;
    for (int c = 0; c < CC; c++) {
        float xv = x0[c];
#pragma unroll
        for (int e = 0; e < 8; e++) lg[e] += xv * G[c * 8 + e];
    }
    float m = lg[0];
#pragma unroll
    for (int e = 1; e < 8; e++) m = fmaxf(m, lg[e]);
    float p[8], sum = 0.f;
#pragma unroll
    for (int e = 0; e < 8; e++) { p[e] = expf(lg[e] - m); sum += p[e]; }
    float inv = 1.f / sum;
#pragma unroll
    for (int e = 0; e < 8; e++) p[e] *= inv;

    // top-2 (ties: lowest index first, matches lax.top_k)
    int i1 = 0;
#pragma unroll
    for (int e = 1; e < 8; e++) if (p[e] > p[i1]) i1 = e;
    int i2 = (i1 == 0) ? 1 : 0;
#pragma unroll
    for (int e = 0; e < 8; e++) { if (e == i1 || e == i2) continue; if (p[e] > p[i2]) i2 = e; }
    float m2 = fmaxf(p[i1], p[i2]);
    float e1 = expf(p[i1] - m2), e2 = expf(p[i2] - m2);
    float winv = 1.f / (e1 + e2);
    float w1 = e1 * winv, w2 = e2 * winv;

    float* wrow = &g_w[(g * 8 + b) * 8];
#pragma unroll
    for (int e = 0; e < 8; e++) wrow[e] = 0.f;
    wrow[i1] = w1;
    wrow[i2] = w2;

    // usage = sum over batch of p
    float u[8];
#pragma unroll
    for (int e = 0; e < 8; e++) {
        u[e] = p[e];
        for (int o = 1; o < 8; o <<= 1) u[e] += __shfl_xor_sync(0xffffffffu, u[e], o);
    }
    __shared__ float sl[4];
    if (b == 0) {
        float mu = 0.f;
#pragma unroll
        for (int e = 0; e < 8; e++) mu += u[e];
        mu *= (1.0f / 8.0f);
        float var = 0.f;
#pragma unroll
        for (int e = 0; e < 8; e++) { float d = u[e] - mu; var += d * d; }
        var *= (1.0f / 7.0f);
        sl[g] = var / (mu * mu + 1e-10f);
    }
    __syncwarp();
    if (lane == 0) loss_out[0] = sl[0] + sl[1] + sl[2] + sl[3];
}

// ---------------------------------------------------------------------------
// Main fused expert kernel (round 2):
//  - 128 threads, 2 CTAs/SM (smem 109.3KB), grid 1024 = b(8) x row(64) x seg(2)
//  - y accumulators live in registers (4 gates x 8co x 4px)
//  - W_caps streamed in 4-ci chunks; W_proj streamed in 32-ci chunks
//  - x window held in regs per ci (3x6), halving b-side LDS
// ---------------------------------------------------------------------------

#define SW_STRIDE 37            // 36 + 1 pad  (4ci x 9 taps)
#define SWBUF     (CC * SW_STRIDE)   // 4736 floats per buffer
#define WP_STRIDE 33            // GEMM2 chunk: 32 ci + 1 pad
#define SU_STRIDE 36            // u tile row stride (16B aligned)

#define OFF_SX    0                       // [128ci][3][34] = 13056
#define OFF_SW    13056                   // 2 x 4736 = 9472
#define OFF_SU    (13056 + 2 * SWBUF)     // 22528, size 128*36 = 4608
#define OFF_SWG   (OFF_SU + CC * SU_STRIDE)   // 27136, 32
#define OFF_SPART (OFF_SWG + 32)          // 27168, 128
#define OFF_SSC   (OFF_SPART + 128)       // 27296, 32
#define SMEM_FLOATS (OFF_SSC + 32)        // 27328
#define SMEM_BYTES  (SMEM_FLOATS * 4)     // 109312

__device__ __forceinline__ uint32_t smem_u32(const void* p) {
    return (uint32_t)__cvta_generic_to_shared(p);
}
__device__ __forceinline__ void cp4(uint32_t dst, const float* src) {
    asm volatile("cp.async.ca.shared.global [%0], [%1], 4;" :: "r"(dst), "l"(src));
}
#define CP_COMMIT() asm volatile("cp.async.commit_group;")
#define CP_WAIT1()  asm volatile("cp.async.wait_group 1;")
#define CP_WAIT0()  asm volatile("cp.async.wait_group 0;")

__global__ void __launch_bounds__(128, 2)
moe_main(const float* __restrict__ x,
         const float* __restrict__ Wc_all, const float* __restrict__ bc_all,
         const float* __restrict__ Wp_all, const float* __restrict__ bp_all,
         float* __restrict__ out) {
    extern __shared__ float sm[];
    float* sx  = sm + OFF_SX;
    float* sw  = sm + OFF_SW;
    float* su  = sm + OFF_SU;
    float* swg = sm + OFF_SWG;
    float* spart = sm + OFF_SPART;
    float* ssc = sm + OFF_SSC;

    const int tid = threadIdx.x;
    const int b   = blockIdx.x >> 7;
    const int t   = blockIdx.x & 127;
    const int row = t >> 1;
    const int seg = t & 1;
    const int cg = tid >> 3, pg = tid & 7;
    const int co_base = cg * 8, px_base = pg * 4;

    // gate weights for this batch
    if (tid < 32) {
        int g = tid >> 3, e = tid & 7;
        swg[tid] = g_w[(g * 8 + b) * 8 + e];
    }
    // load x strip with 1-halo: [ci][rl 0..2][col 0..33]
    {
        const float* xb = x + (size_t)b * IMG;
        for (int i = tid; i < 13056; i += 128) {
            int ci  = i / 102;
            int rem = i - ci * 102;
            int rl  = rem / 34;
            int col = rem - rl * 34;
            int gr = row - 1 + rl;
            int gc = seg * 32 - 1 + col;
            float v = 0.f;
            if ((unsigned)gr < 64u && (unsigned)gc < 64u)
                v = xb[ci * HWPIX + gr * 64 + gc];
            sx[i] = v;
        }
    }
    __syncthreads();

    // per-gate output accumulators in registers
    float yreg[NG][8][4];
#pragma unroll
    for (int g = 0; g < NG; g++)
#pragma unroll
        for (int j = 0; j < 8; j++)
#pragma unroll
            for (int i = 0; i < 4; i++) yreg[g][j][i] = 0.f;

    float acc[8][4];

    for (int e = 0; e < EE; ++e) {
        float wg0 = swg[e], wg1 = swg[8 + e], wg2 = swg[16 + e], wg3 = swg[24 + e];
        if (wg0 == 0.f && wg1 == 0.f && wg2 == 0.f && wg3 == 0.f) continue;

        const float* Wc = Wc_all + (size_t)e * (CC * 1152);

        // ---- GEMM1: u[128co x 32px], K=1152 = 32 chunks of 4 ci (36 floats/co) ----
        // prologue: chunks 0,1
        {
            uint32_t d0 = smem_u32(sw + tid * SW_STRIDE);
            const float* s0 = Wc + (size_t)tid * 1152;
#pragma unroll 9
            for (int r = 0; r < 36; ++r) cp4(d0 + r * 4, s0 + r);
            CP_COMMIT();
            uint32_t d1 = smem_u32(sw + SWBUF + tid * SW_STRIDE);
#pragma unroll 9
            for (int r = 0; r < 36; ++r) cp4(d1 + r * 4, s0 + 36 + r);
            CP_COMMIT();
        }
#pragma unroll
        for (int j = 0; j < 8; j++)
#pragma unroll
            for (int i = 0; i < 4; i++) acc[j][i] = 0.f;

        for (int cc = 0; cc < 32; ++cc) {
            if (cc == 31) { CP_WAIT0(); } else { CP_WAIT1(); }
            __syncthreads();
            const float* wb = sw + (cc & 1) * SWBUF + co_base * SW_STRIDE;
#pragma unroll
            for (int cil = 0; cil < 4; ++cil) {
                const float* xci = sx + (cc * 4 + cil) * 102 + px_base;
                float xr[3][6];
#pragma unroll
                for (int ky = 0; ky < 3; ++ky)
#pragma unroll
                    for (int mm = 0; mm < 6; ++mm) xr[ky][mm] = xci[ky * 34 + mm];
                const float* wci = wb + cil * 9;
#pragma unroll
                for (int ky = 0; ky < 3; ++ky)
#pragma unroll
                    for (int kx = 0; kx < 3; ++kx) {
                        float a[8];
#pragma unroll
                        for (int j = 0; j < 8; j++) a[j] = wci[j * SW_STRIDE + ky * 3 + kx];
#pragma unroll
                        for (int j = 0; j < 8; j++)
#pragma unroll
                            for (int i = 0; i < 4; i++)
                                acc[j][i] = fmaf(a[j], xr[ky][kx + i], acc[j][i]);
                    }
            }
            __syncthreads();
            if (cc + 2 < 32) {
                uint32_t dst = smem_u32(sw + (cc & 1) * SWBUF + tid * SW_STRIDE);
                const float* src = Wc + (size_t)tid * 1152 + (cc + 2) * 36;
#pragma unroll 9
                for (int r = 0; r < 36; ++r) cp4(dst + r * 4, src + r);
                CP_COMMIT();
            }
        }

        // issue W_proj chunks 0,1 (buffers are free after the trailing sync)
        {
            const float* Wp = Wp_all + (size_t)e * 16384;
            uint32_t d0 = smem_u32(sw + tid * WP_STRIDE);
#pragma unroll 8
            for (int r = 0; r < 32; ++r) cp4(d0 + r * 4, Wp + tid * 128 + r);
            CP_COMMIT();
            uint32_t d1 = smem_u32(sw + SWBUF + tid * WP_STRIDE);
#pragma unroll 8
            for (int r = 0; r < 32; ++r) cp4(d1 + r * 4, Wp + tid * 128 + 32 + r);
            CP_COMMIT();
        }

        // bias + store u to smem (vectorized)
#pragma unroll
        for (int j = 0; j < 8; j++) {
            float bj = __ldg(&bc_all[e * CC + co_base + j]);
            float4 v = make_float4(acc[j][0] + bj, acc[j][1] + bj,
                                   acc[j][2] + bj, acc[j][3] + bj);
            *(float4*)&su[(co_base + j) * SU_STRIDE + px_base] = v;
        }
        __syncthreads();

        // squash
        {
            int px = tid & 31, part = tid >> 5;
            float s = 0.f;
#pragma unroll 8
            for (int ci = part * 32; ci < part * 32 + 32; ++ci) {
                float v = su[ci * SU_STRIDE + px];
                s = fmaf(v, v, s);
            }
            spart[part * 32 + px] = s;
        }
        __syncthreads();
        if (tid < 32) {
            float sn = spart[tid] + spart[32 + tid] + spart[64 + tid] + spart[96 + tid];
            ssc[tid] = sn / (1.f + sn) / (sqrtf(sn) + 1e-8f);
        }
        __syncthreads();
        for (int i = tid; i < 4096; i += 128) {
            int ci = i >> 5, px = i & 31;
            su[ci * SU_STRIDE + px] *= ssc[px];
        }

        // ---- GEMM2: v = W_proj @ u, K=128 = 4 chunks of 32 ci ----
#pragma unroll
        for (int j = 0; j < 8; j++)
#pragma unroll
            for (int i = 0; i < 4; i++) acc[j][i] = 0.f;

        const float* Wp = Wp_all + (size_t)e * 16384;
        for (int c2 = 0; c2 < 4; ++c2) {
            if (c2 >= 2) { CP_WAIT0(); } else { CP_WAIT1(); }
            __syncthreads();
            const float* wpb = sw + (c2 & 1) * SWBUF + co_base * WP_STRIDE;
            const float* sub = su + c2 * 32 * SU_STRIDE + px_base;
#pragma unroll 8
            for (int cil = 0; cil < 32; ++cil) {
                float a[8];
#pragma unroll
                for (int j = 0; j < 8; j++) a[j] = wpb[j * WP_STRIDE + cil];
                float4 ub = *(const float4*)&sub[cil * SU_STRIDE];
#pragma unroll
                for (int j = 0; j < 8; j++) {
                    acc[j][0] = fmaf(a[j], ub.x, acc[j][0]);
                    acc[j][1] = fmaf(a[j], ub.y, acc[j][1]);
                    acc[j][2] = fmaf(a[j], ub.z, acc[j][2]);
                    acc[j][3] = fmaf(a[j], ub.w, acc[j][3]);
                }
            }
            __syncthreads();
            if (c2 + 2 < 4) {
                uint32_t dst = smem_u32(sw + (c2 & 1) * SWBUF + tid * WP_STRIDE);
                const float* src = Wp + tid * 128 + (c2 + 2) * 32;
#pragma unroll 8
                for (int r = 0; r < 32; ++r) cp4(dst + r * 4, src + r);
                CP_COMMIT();
            }
        }

        // bias + accumulate weighted output per gate (registers)
#pragma unroll
        for (int j = 0; j < 8; j++) {
            float bj = __ldg(&bp_all[e * CC + co_base + j]);
#pragma unroll
            for (int i = 0; i < 4; i++) {
                float v = acc[j][i] + bj;
                yreg[0][j][i] = fmaf(wg0, v, yreg[0][j][i]);
                yreg[1][j][i] = fmaf(wg1, v, yreg[1][j][i]);
                yreg[2][j][i] = fmaf(wg2, v, yreg[2][j][i]);
                yreg[3][j][i] = fmaf(wg3, v, yreg[3][j][i]);
            }
        }
    }

    // write outputs (STG.128, fully coalesced)
    {
        size_t base = (size_t)b * IMG + (size_t)row * 64 + seg * 32 + px_base;
#pragma unroll
        for (int g = 0; g < NG; ++g) {
            float* og = out + (size_t)g * YSZ + base;
#pragma unroll
            for (int j = 0; j < 8; j++) {
                float4 v = make_float4(yreg[g][j][0], yreg[g][j][1],
                                       yreg[g][j][2], yreg[g][j][3]);
                *(float4*)&og[(size_t)(co_base + j) * HWPIX] = v;
            }
        }
    }
}

// ---------------------------------------------------------------------------
extern "C" void kernel_launch(void* const* d_in, const int* in_sizes, int n_in,
                              void* d_out, int out_size) {
    const float* x  = (const float*)d_in[0];
    const float* g1 = (const float*)d_in[1];
    const float* g2 = (const float*)d_in[2];
    const float* g3 = (const float*)d_in[3];
    const float* g4 = (const float*)d_in[4];
    const float* Wc = (const float*)d_in[5];
    const float* bc = (const float*)d_in[6];
    const float* Wp = (const float*)d_in[7];
    const float* bp = (const float*)d_in[8];
    float* out = (float*)d_out;

    cudaFuncSetAttribute(moe_main, cudaFuncAttributeMaxDynamicSharedMemorySize, SMEM_BYTES);

    mean_kernel<<<BB * CC, 256>>>(x);
    gate_kernel<<<1, 32>>>(g1, g2, g3, g4, out + (out_size - 1));
    moe_main<<<BB * 128, 128, SMEM_BYTES>>>(x, Wc, bc, Wp, bp, out);
}

// round 3
// speedup vs baseline: 3.4384x; 3.4384x over previous
#include <cuda_runtime.h>
#include <cstdint>

// Problem constants
#define CC   128
#define BB   8
#define EE   8
#define NG   4
#define HWPIX 4096
#define IMG  524288   // 128*64*64
#define YSZ  4194304  // 8*128*64*64

__device__ float g_x0[BB * CC];
__device__ float g_w[NG * BB * EE];

// ---------------------------------------------------------------------------
// Kernel 1: x0[b][c] = mean over H,W  (float4 loads)
// ---------------------------------------------------------------------------
__global__ void mean_kernel(const float* __restrict__ x) {
    int bc = blockIdx.x;
    const float4* p = (const float4*)(x + (size_t)bc * HWPIX);
    float s = 0.f;
    for (int i = threadIdx.x; i < 1024; i += 256) {
        float4 v = p[i];
        s += (v.x + v.y) + (v.z + v.w);
    }
    for (int o = 16; o; o >>= 1) s += __shfl_xor_sync(0xffffffffu, s, o);
    __shared__ float sm[8];
    if ((threadIdx.x & 31) == 0) sm[threadIdx.x >> 5] = s;
    __syncthreads();
    if (threadIdx.x < 8) {
        float v = sm[threadIdx.x];
        for (int o = 4; o; o >>= 1) v += __shfl_xor_sync(0xffu, v, o);
        if (threadIdx.x == 0) g_x0[bc] = v * (1.0f / 4096.0f);
    }
}

// ---------------------------------------------------------------------------
// Kernel 2: gates (1 block / 32 threads), writes g_w and loss.
// ---------------------------------------------------------------------------
__global__ void gate_kernel(const float* __restrict__ g1, const float* __restrict__ g2,
                            const float* __restrict__ g3, const float* __restrict__ g4,
                            float* __restrict__ loss_out) {
    int lane = threadIdx.x;
    int g = lane >> 3, b = lane & 7;
    const float* G = (g == 0) ? g1 : (g == 1) ? g2 : (g == 2) ? g3 : g4;
    const float* x0 = &g_x0[b * CC];

    float lg[8];
#pragma unroll
    for (int e = 0; e < 8; e++) lg[e] = 0.f;
    for (int c = 0; c < CC; c++) {
        float xv = x0[c];
#pragma unroll
        for (int e = 0; e < 8; e++) lg[e] += xv * G[c * 8 + e];
    }
    float m = lg[0];
#pragma unroll
    for (int e = 1; e < 8; e++) m = fmaxf(m, lg[e]);
    float p[8], sum = 0.f;
#pragma unroll
    for (int e = 0; e < 8; e++) { p[e] = expf(lg[e] - m); sum += p[e]; }
    float inv = 1.f / sum;
#pragma unroll
    for (int e = 0; e < 8; e++) p[e] *= inv;

    int i1 = 0;
#pragma unroll
    for (int e = 1; e < 8; e++) if (p[e] > p[i1]) i1 = e;
    int i2 = (i1 == 0) ? 1 : 0;
#pragma unroll
    for (int e = 0; e < 8; e++) { if (e == i1 || e == i2) continue; if (p[e] > p[i2]) i2 = e; }
    float m2 = fmaxf(p[i1], p[i2]);
    float e1 = expf(p[i1] - m2), e2 = expf(p[i2] - m2);
    float winv = 1.f / (e1 + e2);

    float* wrow = &g_w[(g * 8 + b) * 8];
#pragma unroll
    for (int e = 0; e < 8; e++) wrow[e] = 0.f;
    wrow[i1] = e1 * winv;
    wrow[i2] = e2 * winv;

    float u[8];
#pragma unroll
    for (int e = 0; e < 8; e++) {
        u[e] = p[e];
        for (int o = 1; o < 8; o <<= 1) u[e] += __shfl_xor_sync(0xffffffffu, u[e], o);
    }
    __shared__ float sl[4];
    if (b == 0) {
        float mu = 0.f;
#pragma unroll
        for (int e = 0; e < 8; e++) mu += u[e];
        mu *= (1.0f / 8.0f);
        float var = 0.f;
#pragma unroll
        for (int e = 0; e < 8; e++) { float d = u[e] - mu; var += d * d; }
        var *= (1.0f / 7.0f);
        sl[g] = var / (mu * mu + 1e-10f);
    }
    __syncwarp();
    if (lane == 0) loss_out[0] = sl[0] + sl[1] + sl[2] + sl[3];
}

// ---------------------------------------------------------------------------
// Main fused kernel (round 3): 256 threads, 1 CTA/SM, full 64-px row/block.
// Grid 512 = b(8) x row(64). Per-thread tile 8co x 4px; y accum in regs.
// ---------------------------------------------------------------------------

#define SW_STRIDE 40                 // GEMM1 weight row: 36 + 4 pad (16B aligned)
#define SWBUF     (CC * SW_STRIDE)   // 5120 floats
#define WP_STRIDE 36                 // GEMM2 weight row: 32 + 4 pad
#define SX_CI     68                 // x cols: 66 used + 2 pad
#define SX_KY     (CC * SX_CI)       // 8704
#define SU_STRIDE 68

#define OFF_SX    0                           // 3*8704 = 26112
#define OFF_SW    26112                       // 2*5120 = 10240
#define OFF_SU    36352                       // 128*68 = 8704
#define OFF_SWG   45056                       // 32
#define OFF_SPART 45088                       // 4*64 = 256
#define OFF_SSC   45344                       // 64
#define SMEM_FLOATS 45408
#define SMEM_BYTES  (SMEM_FLOATS * 4)         // 181632

__device__ __forceinline__ uint32_t smem_u32(const void* p) {
    return (uint32_t)__cvta_generic_to_shared(p);
}
__device__ __forceinline__ void cp16(uint32_t dst, const float* src) {
    asm volatile("cp.async.ca.shared.global [%0], [%1], 16;" :: "r"(dst), "l"(src));
}
#define CP_COMMIT() asm volatile("cp.async.commit_group;")
#define CP_WAIT1()  asm volatile("cp.async.wait_group 1;")
#define CP_WAIT0()  asm volatile("cp.async.wait_group 0;")

// load one 4-ci chunk (36 floats per co) of W_caps into sw buffer
__device__ __forceinline__ void load_wc_chunk(float* buf, const float* Wc,
                                              int chunk, int tid) {
#pragma unroll
    for (int k = 0; k < 5; ++k) {
        int i = tid + k * 256;
        if (i < 1152) {
            int co = i / 9, r = i - co * 9;
            cp16(smem_u32(buf + co * SW_STRIDE + r * 4),
                 Wc + (size_t)co * 1152 + chunk * 36 + r * 4);
        }
    }
}
// load one 32-ci chunk of W_proj into sw buffer (stride 36)
__device__ __forceinline__ void load_wp_chunk(float* buf, const float* Wp,
                                              int chunk, int tid) {
#pragma unroll
    for (int k = 0; k < 4; ++k) {
        int i = tid + k * 256;
        int co = i >> 3, r = i & 7;
        cp16(smem_u32(buf + co * WP_STRIDE + r * 4),
             Wp + co * 128 + chunk * 32 + r * 4);
    }
}

__global__ void __launch_bounds__(256, 1)
moe_main(const float* __restrict__ x,
         const float* __restrict__ Wc_all, const float* __restrict__ bc_all,
         const float* __restrict__ Wp_all, const float* __restrict__ bp_all,
         float* __restrict__ out) {
    extern __shared__ float sm[];
    float* sx  = sm + OFF_SX;
    float* sw  = sm + OFF_SW;
    float* su  = sm + OFF_SU;
    float* swg = sm + OFF_SWG;
    float* spart = sm + OFF_SPART;
    float* ssc = sm + OFF_SSC;

    const int tid = threadIdx.x;
    const int b   = blockIdx.x >> 6;
    const int row = blockIdx.x & 63;
    const int cg = tid >> 4, pg = tid & 15;
    const int co_base = cg * 8, px_base = pg * 4;

    if (tid < 32) {
        int g = tid >> 3, e = tid & 7;
        swg[tid] = g_w[(g * 8 + b) * 8 + e];
    }
    // x strip with halo: sx[ky][ci][col], col 0..65 <-> gc = col-1
    {
        const float* xb = x + (size_t)b * IMG;
        for (int i = tid; i < 3 * SX_KY; i += 256) {
            int ky  = i / SX_KY;
            int rem = i - ky * SX_KY;
            int ci  = rem / SX_CI;
            int col = rem - ci * SX_CI;
            int gr = row - 1 + ky;
            int gc = col - 1;
            float v = 0.f;
            if ((unsigned)gr < 64u && (unsigned)gc < 64u)
                v = xb[ci * HWPIX + gr * 64 + gc];
            sx[i] = v;
        }
    }
    __syncthreads();

    float yreg[NG][8][4];
#pragma unroll
    for (int g = 0; g < NG; g++)
#pragma unroll
        for (int j = 0; j < 8; j++)
#pragma unroll
            for (int i = 0; i < 4; i++) yreg[g][j][i] = 0.f;

    float acc[8][4];

    for (int e = 0; e < EE; ++e) {
        float wg0 = swg[e], wg1 = swg[8 + e], wg2 = swg[16 + e], wg3 = swg[24 + e];
        if (wg0 == 0.f && wg1 == 0.f && wg2 == 0.f && wg3 == 0.f) continue;

        const float* Wc = Wc_all + (size_t)e * (CC * 1152);

        // ---- GEMM1: 128co x 64px, K=1152, 32 chunks of 4 ci ----
        load_wc_chunk(sw, Wc, 0, tid);            CP_COMMIT();
        load_wc_chunk(sw + SWBUF, Wc, 1, tid);    CP_COMMIT();

#pragma unroll
        for (int j = 0; j < 8; j++)
#pragma unroll
            for (int i = 0; i < 4; i++) acc[j][i] = 0.f;

        for (int cc = 0; cc < 32; ++cc) {
            if (cc == 31) { CP_WAIT0(); } else { CP_WAIT1(); }
            __syncthreads();
            const float* wb = sw + (cc & 1) * SWBUF + co_base * SW_STRIDE;
#pragma unroll
            for (int cil = 0; cil < 4; ++cil) {
                const float* xc = sx + (cc * 4 + cil) * SX_CI + px_base;
                float xr[3][8];
#pragma unroll
                for (int ky = 0; ky < 3; ++ky) {
                    float4 u0 = *(const float4*)&xc[ky * SX_KY];
                    float4 u1 = *(const float4*)&xc[ky * SX_KY + 4];
                    xr[ky][0] = u0.x; xr[ky][1] = u0.y; xr[ky][2] = u0.z; xr[ky][3] = u0.w;
                    xr[ky][4] = u1.x; xr[ky][5] = u1.y; xr[ky][6] = u1.z; xr[ky][7] = u1.w;
                }
                const float* wci = wb + cil * 9;
#pragma unroll
                for (int ky = 0; ky < 3; ++ky)
#pragma unroll
                    for (int kx = 0; kx < 3; ++kx) {
                        float a[8];
#pragma unroll
                        for (int j = 0; j < 8; j++) a[j] = wci[j * SW_STRIDE + ky * 3 + kx];
#pragma unroll
                        for (int j = 0; j < 8; j++)
#pragma unroll
                            for (int i = 0; i < 4; i++)
                                acc[j][i] = fmaf(a[j], xr[ky][kx + i], acc[j][i]);
                    }
            }
            __syncthreads();
            if (cc + 2 < 32) {
                load_wc_chunk(sw + (cc & 1) * SWBUF, Wc, cc + 2, tid);
                CP_COMMIT();
            }
        }

        // prefetch W_proj chunks 0,1 (overlaps squash)
        const float* Wp = Wp_all + (size_t)e * 16384;
        load_wp_chunk(sw, Wp, 0, tid);          CP_COMMIT();
        load_wp_chunk(sw + SWBUF, Wp, 1, tid);  CP_COMMIT();

        // bias + store u
#pragma unroll
        for (int j = 0; j < 8; j++) {
            float bj = __ldg(&bc_all[e * CC + co_base + j]);
            float4 v = make_float4(acc[j][0] + bj, acc[j][1] + bj,
                                   acc[j][2] + bj, acc[j][3] + bj);
            *(float4*)&su[(co_base + j) * SU_STRIDE + px_base] = v;
        }
        __syncthreads();

        // squash
        {
            int px = tid & 63, part = tid >> 6;
            float s = 0.f;
#pragma unroll 8
            for (int ci = part * 32; ci < part * 32 + 32; ++ci) {
                float v = su[ci * SU_STRIDE + px];
                s = fmaf(v, v, s);
            }
            spart[part * 64 + px] = s;
        }
        __syncthreads();
        if (tid < 64) {
            float sn = spart[tid] + spart[64 + tid] + spart[128 + tid] + spart[192 + tid];
            ssc[tid] = sn / (1.f + sn) / (sqrtf(sn) + 1e-8f);
        }
        __syncthreads();
        for (int i = tid; i < 2048; i += 256) {
            int ci = i >> 4, p4 = (i & 15) * 4;
            float4 v = *(float4*)&su[ci * SU_STRIDE + p4];
            float4 s4 = *(const float4*)&ssc[p4];
            v.x *= s4.x; v.y *= s4.y; v.z *= s4.z; v.w *= s4.w;
            *(float4*)&su[ci * SU_STRIDE + p4] = v;
        }

        // ---- GEMM2: K=128, 4 chunks of 32 ci ----
#pragma unroll
        for (int j = 0; j < 8; j++)
#pragma unroll
            for (int i = 0; i < 4; i++) acc[j][i] = 0.f;

        for (int c2 = 0; c2 < 4; ++c2) {
            if (c2 == 3) { CP_WAIT0(); } else { CP_WAIT1(); }
            __syncthreads();
            const float* wpb = sw + (c2 & 1) * SWBUF + co_base * WP_STRIDE;
            const float* sub = su + c2 * 32 * SU_STRIDE + px_base;
#pragma unroll 8
            for (int cil = 0; cil < 32; ++cil) {
                float a[8];
#pragma unroll
                for (int j = 0; j < 8; j++) a[j] = wpb[j * WP_STRIDE + cil];
                float4 ub = *(const float4*)&sub[cil * SU_STRIDE];
#pragma unroll
                for (int j = 0; j < 8; j++) {
                    acc[j][0] = fmaf(a[j], ub.x, acc[j][0]);
                    acc[j][1] = fmaf(a[j], ub.y, acc[j][1]);
                    acc[j][2] = fmaf(a[j], ub.z, acc[j][2]);
                    acc[j][3] = fmaf(a[j], ub.w, acc[j][3]);
                }
            }
            __syncthreads();
            if (c2 + 2 < 4) {
                load_wp_chunk(sw + (c2 & 1) * SWBUF, Wp, c2 + 2, tid);
                CP_COMMIT();
            }
        }

        // bias + gate-weighted accumulation into registers
#pragma unroll
        for (int j = 0; j < 8; j++) {
            float bj = __ldg(&bp_all[e * CC + co_base + j]);
#pragma unroll
            for (int i = 0; i < 4; i++) {
                float v = acc[j][i] + bj;
                yreg[0][j][i] = fmaf(wg0, v, yreg[0][j][i]);
                yreg[1][j][i] = fmaf(wg1, v, yreg[1][j][i]);
                yreg[2][j][i] = fmaf(wg2, v, yreg[2][j][i]);
                yreg[3][j][i] = fmaf(wg3, v, yreg[3][j][i]);
            }
        }
    }

    // write outputs (STG.128, coalesced)
    {
        size_t base = (size_t)b * IMG + (size_t)row * 64 + px_base;
#pragma unroll
        for (int g = 0; g < NG; ++g) {
            float* og = out + (size_t)g * YSZ + base;
#pragma unroll
            for (int j = 0; j < 8; j++) {
                float4 v = make_float4(yreg[g][j][0], yreg[g][j][1],
                                       yreg[g][j][2], yreg[g][j][3]);
                *(float4*)&og[(size_t)(co_base + j) * HWPIX] = v;
            }
        }
    }
}

// ---------------------------------------------------------------------------
extern "C" void kernel_launch(void* const* d_in, const int* in_sizes, int n_in,
                              void* d_out, int out_size) {
    const float* x  = (const float*)d_in[0];
    const float* g1 = (const float*)d_in[1];
    const float* g2 = (const float*)d_in[2];
    const float* g3 = (const float*)d_in[3];
    const float* g4 = (const float*)d_in[4];
    const float* Wc = (const float*)d_in[5];
    const float* bc = (const float*)d_in[6];
    const float* Wp = (const float*)d_in[7];
    const float* bp = (const float*)d_in[8];
    float* out = (float*)d_out;

    cudaFuncSetAttribute(moe_main, cudaFuncAttributeMaxDynamicSharedMemorySize, SMEM_BYTES);

    mean_kernel<<<BB * CC, 256>>>(x);
    gate_kernel<<<1, 32>>>(g1, g2, g3, g4, out + (out_size - 1));
    moe_main<<<512, 256, SMEM_BYTES>>>(x, Wc, bc, Wp, bp, out);
}